// round 11
// baseline (speedup 1.0000x reference)
#include <cuda_runtime.h>
#include <cuda_bf16.h>

// ---------------- problem constants ----------------
constexpr int LSEQ = 2048;   // sequence length
constexpr int DDIM = 512;    // model dim (also N of all GEMMs)
constexpr int SDIM = 512;    // state dim
constexpr int NK   = 24;     // K (half of channels)
constexpr int TWOK = 48;     // 2K channels
constexpr int KXC  = 16;     // FIR taps
constexpr int TCH  = 64;     // chunk length
constexpr int NCH  = LSEQ / TCH;        // 32 chunks
constexpr int RC   = TCH * TWOK;        // 3072 rows per chunk-GEMM
constexpr int KC   = SDIM + 16 + TCH;   // 592 = state + prev-16 inputs + chunk inputs
constexpr int KF   = TWOK * DDIM;       // 24576 final-GEMM K
constexpr int NSPL = 4;                 // split-K for final GEMM
constexpr int KSPL = KF / NSPL;         // 6144

// ---------------- device scratch (static; no allocs allowed) ----------------
__device__ float d_Apow[(TCH + 1) * SDIM];          // A^tau, tau in [0,64]
__device__ float d_Kbase[TWOK * TCH];               // sum_s A^tau B C
__device__ float d_Qmat[SDIM * TCH];                // A^{63-delta}
__device__ float d_Wbig[RC * KC];                   // fused chunk LHS (7.3 MB)
__device__ float d_R[NCH * SDIM * DDIM];            // per-chunk state increments
__device__ float d_Gp[NCH * SDIM * DDIM];           // state before each chunk
__device__ float d_U[(size_t)LSEQ * TWOK * DDIM];   // U[t][j][n] (201 MB)
__device__ float d_Upart[NSPL * LSEQ * DDIM];       // split-K partials
__device__ const float* g_pA;
__device__ const float* g_pB;

// ---------------- pick A vs B_in by value (A in (0.8,0.999); B_in ~ N(0,1/512)) ----
__global__ void pick_AB(const float* c0, const float* c1) {
    bool ok = true;
    for (int s = 0; s < SDIM; s++) {
        float v = c0[s];
        if (v < 0.5f || v > 1.0f) { ok = false; break; }
    }
    if (ok) { g_pA = c0; g_pB = c1; }
    else    { g_pA = c1; g_pB = c0; }
}

// ---------------- prep kernels ----------------
__global__ void prep_pow() {
    int s = threadIdx.x;              // 512 threads
    float a = g_pA[s];
    float p = 1.f;
    for (int t = 0; t <= TCH; t++) { d_Apow[t * SDIM + s] = p; p *= a; }
}

__global__ void prep_kbase(const float* __restrict__ C) {
    int id = blockIdx.x * blockDim.x + threadIdx.x;
    if (id >= TWOK * TCH) return;
    int j = id / TCH, tau = id % TCH;
    const float* B_in = g_pB;
    float acc = 0.f;
    for (int s = 0; s < SDIM; s++)
        acc += d_Apow[tau * SDIM + s] * B_in[s] * C[s * TWOK + j];
    d_Kbase[id] = acc;                // Kbase[j][tau]
}

__global__ void prep_qmat() {
    int id = blockIdx.x * blockDim.x + threadIdx.x;
    if (id >= SDIM * TCH) return;
    int s = id / TCH, dlt = id % TCH;
    d_Qmat[id] = d_Apow[(TCH - 1 - dlt) * SDIM + s];
}

__global__ void prep_wbig(const float* __restrict__ C, const float* __restrict__ M) {
    int id = blockIdx.x * blockDim.x + threadIdx.x;
    if (id >= RC * KC) return;
    int r = id / KC, k = id % KC;
    int dlt = r / TWOK, j = r % TWOK;
    float v;
    if (k < SDIM) {
        // inter-chunk: A^{delta+1} * B_in[s] * C[s][j]
        v = d_Apow[(dlt + 1) * SDIM + k] * g_pB[k] * C[k * TWOK + j];
    } else {
        int dp = (k - SDIM) - 16;     // delta' relative to chunk start (may be < 0)
        int tau = dlt - dp;
        v = 0.f;
        if (tau >= 0) {
            if (dp >= 0) v += d_Kbase[j * TCH + tau];   // LDS kernel (intra-chunk only)
            if (tau < KXC) v += M[j * KXC + tau];       // FIR taps (incl. boundary tail)
        }
    }
    d_Wbig[id] = v;
}

// ---------------- loader functors ----------------
struct LA_Qmat {
    __device__ float operator()(int m, int k, int /*z*/) const { return d_Qmat[m * TCH + k]; }
};
struct LA_Wbig {
    __device__ float operator()(int m, int k, int /*z*/) const { return d_Wbig[(size_t)m * KC + k]; }
};
struct LA_U {
    __device__ float operator()(int m, int k, int /*z*/) const { return d_U[(size_t)m * KF + k]; }
};
struct LB_X {        // B for state-increment GEMM: x rows of chunk z
    const float* x;
    __device__ float operator()(int k, int n, int z) const {
        return x[((size_t)z * TCH + k) * DDIM + n];
    }
};
struct LB_Chunk {    // B for fused chunk GEMM: [Gp(z) ; x rows zT-16 .. zT+63]
    const float* x;
    __device__ float operator()(int k, int n, int z) const {
        if (k < SDIM) return d_Gp[((size_t)z * SDIM + k) * DDIM + n];
        int t = z * TCH - 16 + (k - SDIM);
        return (t >= 0) ? x[(size_t)t * DDIM + n] : 0.f;
    }
};
struct LB_Phi {      // B for final GEMM: [M_phi_plus ; M_phi_minus] flattened over (j,n)
    const float* mp; const float* mm;
    __device__ float operator()(int k, int n, int /*z*/) const {
        return (k < NK * DDIM) ? mp[(size_t)k * DDIM + n]
                               : mm[(size_t)(k - NK * DDIM) * DDIM + n];
    }
};

// ---------------- generic 128x64 fp32 tile GEMM ----------------
template <typename LA, typename LB, bool SPLITK>
__global__ __launch_bounds__(256) void gemm_tmpl(LA la, LB lb, float* Cbase,
                                                 size_t czstride, int N, int Ktot) {
    __shared__ float As[16][132];
    __shared__ float Bs[16][68];
    int z = blockIdx.z;
    int kbeg = SPLITK ? z * Ktot : 0;
    int kend = kbeg + Ktot;
    float* Cout = Cbase + (size_t)z * czstride;

    int tid = threadIdx.x;
    int tx = tid & 15;    // n-group (x4)
    int ty = tid >> 4;    // m-group (x8)
    int m0 = blockIdx.y * 128;
    int n0 = blockIdx.x * 64;

    float acc[8][4];
#pragma unroll
    for (int i = 0; i < 8; i++)
#pragma unroll
        for (int j = 0; j < 4; j++) acc[i][j] = 0.f;

    for (int k0 = kbeg; k0 < kend; k0 += 16) {
#pragma unroll
        for (int i = 0; i < 8; i++) {             // 128x16 A tile
            int e = tid + i * 256;
            int m = e >> 4, k = e & 15;
            As[k][m] = la(m0 + m, k0 + k, z);
        }
#pragma unroll
        for (int i = 0; i < 4; i++) {             // 16x64 B tile
            int e = tid + i * 256;
            int k = e >> 6, n = e & 63;
            Bs[k][n] = lb(k0 + k, n0 + n, z);
        }
        __syncthreads();
#pragma unroll
        for (int k = 0; k < 16; k++) {
            float4 a0 = *reinterpret_cast<const float4*>(&As[k][ty * 8]);
            float4 a1 = *reinterpret_cast<const float4*>(&As[k][ty * 8 + 4]);
            float4 b0 = *reinterpret_cast<const float4*>(&Bs[k][tx * 4]);
            float ra[8] = {a0.x, a0.y, a0.z, a0.w, a1.x, a1.y, a1.z, a1.w};
            float rb[4] = {b0.x, b0.y, b0.z, b0.w};
#pragma unroll
            for (int i = 0; i < 8; i++)
#pragma unroll
                for (int j = 0; j < 4; j++) acc[i][j] += ra[i] * rb[j];
        }
        __syncthreads();
    }
#pragma unroll
    for (int i = 0; i < 8; i++) {
        int row = m0 + ty * 8 + i;
        float4 v = make_float4(acc[i][0], acc[i][1], acc[i][2], acc[i][3]);
        *reinterpret_cast<float4*>(&Cout[(size_t)row * N + n0 + tx * 4]) = v;
    }
}

// ---------------- scan over chunks (state carry) ----------------
__global__ void scan_chunks() {
    int idx = blockIdx.x * blockDim.x + threadIdx.x;   // (s,n), 262144 threads
    if (idx >= SDIM * DDIM) return;
    int s = idx >> 9;
    float at = d_Apow[TCH * SDIM + s];   // A^T
    float g = 0.f;
    d_Gp[idx] = 0.f;                     // state before chunk 0
    for (int c = 1; c < NCH; c++) {
        g = at * g + d_R[(size_t)(c - 1) * SDIM * DDIM + idx];
        d_Gp[(size_t)c * SDIM * DDIM + idx] = g;
    }
}

// ---------------- split-K reduce -> bf16-quantized FLOAT32 output ----------------
// KEY FIX: the harness output buffer is float32 (upcast of the reference's bf16
// values). Write f32, rounded through bf16 to match the reference quantization.
__global__ void reduce_out(float* __restrict__ out) {
    int i = blockIdx.x * blockDim.x + threadIdx.x;
    if (i >= LSEQ * DDIM) return;
    float v = d_Upart[i] + d_Upart[LSEQ * DDIM + i] +
              d_Upart[2 * LSEQ * DDIM + i] + d_Upart[3 * LSEQ * DDIM + i];
    out[i] = __bfloat162float(__float2bfloat16(v));
}

// ---------------- launch ----------------
extern "C" void kernel_launch(void* const* d_in, const int* in_sizes, int n_in,
                              void* d_out, int out_size) {
    // size-based identification; A/B disambiguated on device by value
    int ix = -1, ipos = -1, iC = -1, iM = -1, i512a = -1, i512b = -1, iph1 = -1, iph2 = -1;
    for (int i = 0; i < n_in; i++) {
        int s = in_sizes[i];
        if (s == 1048576)      ix = i;
        else if (s == 2048)    ipos = i;
        else if (s == 24576)   iC = i;
        else if (s == 768)     iM = i;
        else if (s == 512)     { if (i512a < 0) i512a = i; else i512b = i; }
        else if (s == 6291456) { if (iph1 < 0) iph1 = i; else iph2 = i; }
    }
    int iMp, iMm;
    if (iph1 > ipos) { iMp = iph1; iMm = iph2; }   // dict order: plus first
    else             { iMm = iph1; iMp = iph2; }   // alphabetical: minus first

    const float* x    = (const float*)d_in[ix];
    const float* c0   = (const float*)d_in[i512a];
    const float* c1   = (const float*)d_in[i512b];
    const float* C    = (const float*)d_in[iC];
    const float* M    = (const float*)d_in[iM];
    const float* Mp   = (const float*)d_in[iMp];
    const float* Mm   = (const float*)d_in[iMm];
    float* out        = (float*)d_out;
    (void)out_size;

    float *pR, *pU, *pUpart;
    cudaGetSymbolAddress((void**)&pR, d_R);
    cudaGetSymbolAddress((void**)&pU, d_U);
    cudaGetSymbolAddress((void**)&pUpart, d_Upart);

    // prep
    pick_AB<<<1, 1>>>(c0, c1);
    prep_pow<<<1, 512>>>();
    prep_kbase<<<(TWOK * TCH + 255) / 256, 256>>>(C);
    prep_qmat<<<(SDIM * TCH + 255) / 256, 256>>>();
    prep_wbig<<<(RC * KC + 255) / 256, 256>>>(C, M);

    // 1) per-chunk state increments: R[c] = Qmat(512x64) @ X_c(64x512)
    {
        LA_Qmat la; LB_X lb{x};
        dim3 grid(DDIM / 64, SDIM / 128, NCH);
        gemm_tmpl<LA_Qmat, LB_X, false><<<grid, 256>>>(la, lb, pR,
            (size_t)SDIM * DDIM, DDIM, TCH);
    }
    // 2) chunk-state scan
    scan_chunks<<<(SDIM * DDIM + 255) / 256, 256>>>();

    // 3) fused chunk GEMM: U_c(3072x512) = Wbig(3072x592) @ [Gp_c ; x tail ; x chunk]
    {
        LA_Wbig la; LB_Chunk lb{x};
        dim3 grid(DDIM / 64, RC / 128, NCH);
        gemm_tmpl<LA_Wbig, LB_Chunk, false><<<grid, 256>>>(la, lb, pU,
            (size_t)RC * DDIM, DDIM, KC);
    }

    // 4) final einsum: out(2048x512) = U(2048x24576) @ [Mphi+;Mphi-] (split-K=4)
    {
        LA_U la; LB_Phi lb{Mp, Mm};
        dim3 grid(DDIM / 64, LSEQ / 128, NSPL);
        gemm_tmpl<LA_U, LB_Phi, true><<<grid, 256>>>(la, lb, pUpart,
            (size_t)LSEQ * DDIM, DDIM, KSPL);
    }

    // 5) reduce splits -> f32 output (bf16-quantized values)
    reduce_out<<<(LSEQ * DDIM + 255) / 256, 256>>>(out);
}

// round 13
// speedup vs baseline: 2.7444x; 2.7444x over previous
#include <cuda_runtime.h>
#include <cuda_bf16.h>
#include <cstdint>

// ---------------- problem constants ----------------
constexpr int LSEQ = 2048;
constexpr int DDIM = 512;
constexpr int SDIM = 512;
constexpr int NK   = 24;
constexpr int TWOK = 48;
constexpr int KXC  = 16;
constexpr int TCH  = 64;
constexpr int NCH  = LSEQ / TCH;        // 32
constexpr int RC   = TCH * TWOK;        // 3072
constexpr int KC   = SDIM + 16 + TCH;   // 592
constexpr int KCP  = 608;               // 592 padded to 32
constexpr int KF   = TWOK * DDIM;       // 24576
constexpr int NSPL = 8;                 // split-K for final GEMM
constexpr int KSPL = KF / NSPL;         // 3072

// smem strides (bf16 elems) — conflict-free for ldmatrix
constexpr int SA = 40;    // A tile row stride (80 B)
constexpr int SB = 136;   // B tile row stride (272 B)

// ---------------- device scratch ----------------
__device__ __align__(16) float d_Apow[(TCH + 1) * SDIM];
__device__ __align__(16) float d_Kbase[TWOK * TCH];
__device__ __align__(16) float d_Qmat[SDIM * TCH];
__device__ __align__(16) float d_R[NCH * SDIM * DDIM];
__device__ __align__(16) float d_Gp[NCH * SDIM * DDIM];
__device__ __align__(16) __nv_bfloat16 d_Wh[RC * KCP];            // Wbig split
__device__ __align__(16) __nv_bfloat16 d_Wl[RC * KCP];
__device__ __align__(16) __nv_bfloat16 d_Bh[NCH * KCP * DDIM];    // chunk RHS split
__device__ __align__(16) __nv_bfloat16 d_Bl[NCH * KCP * DDIM];
__device__ __align__(16) __nv_bfloat16 d_Uh[(size_t)LSEQ * KF];   // U split (100.7 MB each)
__device__ __align__(16) __nv_bfloat16 d_Ul[(size_t)LSEQ * KF];
__device__ __align__(16) __nv_bfloat16 d_Ph[(size_t)KF * DDIM];   // Phi split
__device__ __align__(16) __nv_bfloat16 d_Pl[(size_t)KF * DDIM];
__device__ __align__(16) float d_Upart[NSPL * LSEQ * DDIM];
__device__ const float* g_pA;
__device__ const float* g_pB;

__device__ __forceinline__ void split2(float v, __nv_bfloat16& h, __nv_bfloat16& l) {
    h = __float2bfloat16(v);
    l = __float2bfloat16(v - __bfloat162float(h));
}

// ---------------- pick A vs B_in by value ----------------
__global__ void pick_AB(const float* c0, const float* c1) {
    bool ok = true;
    for (int s = 0; s < SDIM; s++) {
        float v = c0[s];
        if (v < 0.5f || v > 1.0f) { ok = false; break; }
    }
    if (ok) { g_pA = c0; g_pB = c1; } else { g_pA = c1; g_pB = c0; }
}

// ---------------- prep ----------------
__global__ void prep_pow() {
    int s = threadIdx.x;
    float a = g_pA[s], p = 1.f;
    for (int t = 0; t <= TCH; t++) { d_Apow[t * SDIM + s] = p; p *= a; }
}

__global__ void prep_kbase(const float* __restrict__ C) {
    int id = blockIdx.x * blockDim.x + threadIdx.x;
    if (id >= TWOK * TCH) return;
    int j = id / TCH, tau = id % TCH;
    const float* B_in = g_pB;
    float acc = 0.f;
    for (int s = 0; s < SDIM; s++)
        acc += d_Apow[tau * SDIM + s] * B_in[s] * C[s * TWOK + j];
    d_Kbase[id] = acc;
}

__global__ void prep_qmat() {
    int id = blockIdx.x * blockDim.x + threadIdx.x;
    if (id >= SDIM * TCH) return;
    int s = id / TCH, dlt = id % TCH;
    d_Qmat[id] = d_Apow[(TCH - 1 - dlt) * SDIM + s];
}

__global__ void prep_wbig(const float* __restrict__ C, const float* __restrict__ M) {
    int id = blockIdx.x * blockDim.x + threadIdx.x;
    if (id >= RC * KCP) return;
    int r = id / KCP, k = id % KCP;
    int dlt = r / TWOK, j = r % TWOK;
    float v = 0.f;
    if (k < SDIM) {
        v = d_Apow[(dlt + 1) * SDIM + k] * g_pB[k] * C[k * TWOK + j];
    } else if (k < KC) {
        int dp = (k - SDIM) - 16;
        int tau = dlt - dp;
        if (tau >= 0) {
            if (dp >= 0) v += d_Kbase[j * TCH + tau];
            if (tau < KXC) v += M[j * KXC + tau];
        }
    }
    split2(v, d_Wh[id], d_Wl[id]);
}

// chunk RHS: rows 0-511 = Gp(z), 512-527 = x tail, 528-591 = x chunk, 592-607 = 0
__global__ void prep_bmat(const float* __restrict__ x) {
    int id = blockIdx.x * blockDim.x + threadIdx.x;
    if (id >= NCH * KCP * DDIM) return;
    int n = id % DDIM;
    int k = (id / DDIM) % KCP;
    int z = id / (KCP * DDIM);
    float v = 0.f;
    if (k < SDIM) v = d_Gp[((size_t)z * SDIM + k) * DDIM + n];
    else if (k < KC) {
        int t = z * TCH - 16 + (k - SDIM);
        if (t >= 0) v = x[(size_t)t * DDIM + n];
    }
    split2(v, d_Bh[id], d_Bl[id]);
}

__global__ void prep_phi(const float* __restrict__ Mp, const float* __restrict__ Mm) {
    size_t id = (size_t)blockIdx.x * blockDim.x + threadIdx.x;
    if (id >= (size_t)KF * DDIM) return;
    size_t half = (size_t)NK * DDIM * DDIM;
    float v = (id < half) ? Mp[id] : Mm[id - half];
    split2(v, d_Ph[id], d_Pl[id]);
}

// ---------------- GEMM-1 (small, exact fp32 SIMT) ----------------
struct LA_Qmat { __device__ float operator()(int m, int k, int) const { return d_Qmat[m * TCH + k]; } };
struct LB_X {
    const float* x;
    __device__ float operator()(int k, int n, int z) const {
        return x[((size_t)z * TCH + k) * DDIM + n];
    }
};
template <typename LA, typename LB>
__global__ __launch_bounds__(256) void gemm_f32(LA la, LB lb, float* Cbase,
                                                size_t czstride, int N, int Ktot) {
    __shared__ float As[16][132];
    __shared__ float Bs[16][68];
    int z = blockIdx.z;
    float* Cout = Cbase + (size_t)z * czstride;
    int tid = threadIdx.x, tx = tid & 15, ty = tid >> 4;
    int m0 = blockIdx.y * 128, n0 = blockIdx.x * 64;
    float acc[8][4];
#pragma unroll
    for (int i = 0; i < 8; i++)
#pragma unroll
        for (int j = 0; j < 4; j++) acc[i][j] = 0.f;
    for (int k0 = 0; k0 < Ktot; k0 += 16) {
#pragma unroll
        for (int i = 0; i < 8; i++) {
            int e = tid + i * 256; int m = e >> 4, k = e & 15;
            As[k][m] = la(m0 + m, k0 + k, z);
        }
#pragma unroll
        for (int i = 0; i < 4; i++) {
            int e = tid + i * 256; int k = e >> 6, n = e & 63;
            Bs[k][n] = lb(k0 + k, n0 + n, z);
        }
        __syncthreads();
#pragma unroll
        for (int k = 0; k < 16; k++) {
            float4 a0 = *reinterpret_cast<const float4*>(&As[k][ty * 8]);
            float4 a1 = *reinterpret_cast<const float4*>(&As[k][ty * 8 + 4]);
            float4 b0 = *reinterpret_cast<const float4*>(&Bs[k][tx * 4]);
            float ra[8] = {a0.x, a0.y, a0.z, a0.w, a1.x, a1.y, a1.z, a1.w};
            float rb[4] = {b0.x, b0.y, b0.z, b0.w};
#pragma unroll
            for (int i = 0; i < 8; i++)
#pragma unroll
                for (int j = 0; j < 4; j++) acc[i][j] += ra[i] * rb[j];
        }
        __syncthreads();
    }
#pragma unroll
    for (int i = 0; i < 8; i++) {
        int row = m0 + ty * 8 + i;
        float4 v = make_float4(acc[i][0], acc[i][1], acc[i][2], acc[i][3]);
        *reinterpret_cast<float4*>(&Cout[(size_t)row * N + n0 + tx * 4]) = v;
    }
}

__global__ void scan_chunks() {
    int idx = blockIdx.x * blockDim.x + threadIdx.x;
    if (idx >= SDIM * DDIM) return;
    int s = idx >> 9;
    float at = d_Apow[TCH * SDIM + s];
    float g = 0.f;
    d_Gp[idx] = 0.f;
    for (int c = 1; c < NCH; c++) {
        g = at * g + d_R[(size_t)(c - 1) * SDIM * DDIM + idx];
        d_Gp[(size_t)c * SDIM * DDIM + idx] = g;
    }
}

// ---------------- mma.sync bf16 GEMM, 3-term compensated ----------------
__device__ __forceinline__ uint32_t s2u(const void* p) {
    return (uint32_t)__cvta_generic_to_shared(p);
}
__device__ __forceinline__ void ldm4(uint32_t* d, uint32_t a) {
    asm volatile("ldmatrix.sync.aligned.m8n8.x4.shared.b16 {%0,%1,%2,%3}, [%4];\n"
                 : "=r"(d[0]), "=r"(d[1]), "=r"(d[2]), "=r"(d[3]) : "r"(a));
}
__device__ __forceinline__ void ldm4t(uint32_t* d, uint32_t a) {
    asm volatile("ldmatrix.sync.aligned.m8n8.x4.trans.shared.b16 {%0,%1,%2,%3}, [%4];\n"
                 : "=r"(d[0]), "=r"(d[1]), "=r"(d[2]), "=r"(d[3]) : "r"(a));
}
__device__ __forceinline__ void mma16816(float* c, const uint32_t* a, uint32_t b0, uint32_t b1) {
    asm volatile("mma.sync.aligned.m16n8k16.row.col.f32.bf16.bf16.f32 "
                 "{%0,%1,%2,%3}, {%4,%5,%6,%7}, {%8,%9}, {%0,%1,%2,%3};\n"
                 : "+f"(c[0]), "+f"(c[1]), "+f"(c[2]), "+f"(c[3])
                 : "r"(a[0]), "r"(a[1]), "r"(a[2]), "r"(a[3]), "r"(b0), "r"(b1));
}

// EPI=0: split-bf16 epilogue to (o1=Uh, o2=Ul). EPI=1: f32 epilogue to o1.
// Per z: A += aZ, B += bZ*z (elements), C += cZ*z.
template <int EPI>
__global__ __launch_bounds__(256) void mma_gemm(
    const __nv_bfloat16* __restrict__ Ah, const __nv_bfloat16* __restrict__ Al, int lda, long aZ,
    const __nv_bfloat16* __restrict__ Bh, const __nv_bfloat16* __restrict__ Bl, int ldb, long bZ,
    void* o1, void* o2, int ldc, long cZ, int kIters) {
    __shared__ __align__(16) __nv_bfloat16 Ash[128 * SA];
    __shared__ __align__(16) __nv_bfloat16 Asl[128 * SA];
    __shared__ __align__(16) __nv_bfloat16 Bsh[32 * SB];
    __shared__ __align__(16) __nv_bfloat16 Bsl[32 * SB];

    int z = blockIdx.z;
    Ah += (size_t)z * aZ; Al += (size_t)z * aZ;
    Bh += (size_t)z * bZ; Bl += (size_t)z * bZ;

    int tid = threadIdx.x;
    int lane = tid & 31, warp = tid >> 5;
    int wm = warp & 3, wn = warp >> 2;          // 4x2 warp grid
    int m0 = blockIdx.y * 128, n0 = blockIdx.x * 128;

    float acc[2][8][4];
#pragma unroll
    for (int a = 0; a < 2; a++)
#pragma unroll
        for (int b = 0; b < 8; b++)
#pragma unroll
            for (int c = 0; c < 4; c++) acc[a][b][c] = 0.f;

    for (int it = 0; it < kIters; it++) {
        int k0 = it * 32;
        // load A 128x32 (hi+lo)
        {
            int r = tid >> 2, c = (tid & 3) * 8;
#pragma unroll
            for (int p = 0; p < 2; p++) {
                int row = r + p * 64;
                const uint4* gh = reinterpret_cast<const uint4*>(Ah + (size_t)(m0 + row) * lda + k0 + c);
                const uint4* gl = reinterpret_cast<const uint4*>(Al + (size_t)(m0 + row) * lda + k0 + c);
                *reinterpret_cast<uint4*>(&Ash[row * SA + c]) = *gh;
                *reinterpret_cast<uint4*>(&Asl[row * SA + c]) = *gl;
            }
        }
        // load B 32x128 (hi+lo)
        {
            int r = tid >> 4, c = (tid & 15) * 8;
#pragma unroll
            for (int p = 0; p < 2; p++) {
                int row = r + p * 16;
                const uint4* gh = reinterpret_cast<const uint4*>(Bh + (size_t)(k0 + row) * ldb + n0 + c);
                const uint4* gl = reinterpret_cast<const uint4*>(Bl + (size_t)(k0 + row) * ldb + n0 + c);
                *reinterpret_cast<uint4*>(&Bsh[row * SB + c]) = *gh;
                *reinterpret_cast<uint4*>(&Bsl[row * SB + c]) = *gl;
            }
        }
        __syncthreads();

#pragma unroll
        for (int ks = 0; ks < 2; ks++) {
            uint32_t ah[2][4], al[2][4];
#pragma unroll
            for (int mt = 0; mt < 2; mt++) {
                int row = wm * 32 + mt * 16 + (lane & 15);
                int col = ks * 16 + (lane >> 4) * 8;
                ldm4(ah[mt], s2u(&Ash[row * SA + col]));
                ldm4(al[mt], s2u(&Asl[row * SA + col]));
            }
#pragma unroll
            for (int nt = 0; nt < 4; nt++) {
                int lr = ks * 16 + ((lane >> 3) & 1) * 8 + (lane & 7);
                int lc = wn * 64 + nt * 16 + (lane >> 4) * 8;
                uint32_t bh[4], bl[4];
                ldm4t(bh, s2u(&Bsh[lr * SB + lc]));
                ldm4t(bl, s2u(&Bsl[lr * SB + lc]));
#pragma unroll
                for (int mt = 0; mt < 2; mt++) {
#pragma unroll
                    for (int hf = 0; hf < 2; hf++) {
                        float* c = acc[mt][nt * 2 + hf];
                        mma16816(c, ah[mt], bh[2 * hf], bh[2 * hf + 1]);
                        mma16816(c, ah[mt], bl[2 * hf], bl[2 * hf + 1]);
                        mma16816(c, al[mt], bh[2 * hf], bh[2 * hf + 1]);
                    }
                }
            }
        }
        __syncthreads();
    }

    // epilogue
#pragma unroll
    for (int mt = 0; mt < 2; mt++) {
#pragma unroll
        for (int nb = 0; nb < 8; nb++) {
            int row = m0 + wm * 32 + mt * 16 + (lane >> 2);
            int col = n0 + wn * 64 + nb * 8 + (lane & 3) * 2;
            float v0 = acc[mt][nb][0], v1 = acc[mt][nb][1];
            float v2 = acc[mt][nb][2], v3 = acc[mt][nb][3];
            if (EPI == 0) {
                __nv_bfloat16* Uh = (__nv_bfloat16*)o1;
                __nv_bfloat16* Ul = (__nv_bfloat16*)o2;
                size_t i0 = (size_t)z * cZ + (size_t)row * ldc + col;
                size_t i1 = i0 + (size_t)8 * ldc;
                __nv_bfloat16 h0, l0, h1, l1;
                split2(v0, h0, l0); split2(v1, h1, l1);
                *reinterpret_cast<__nv_bfloat162*>(&Uh[i0]) = __nv_bfloat162(h0, h1);
                *reinterpret_cast<__nv_bfloat162*>(&Ul[i0]) = __nv_bfloat162(l0, l1);
                split2(v2, h0, l0); split2(v3, h1, l1);
                *reinterpret_cast<__nv_bfloat162*>(&Uh[i1]) = __nv_bfloat162(h0, h1);
                *reinterpret_cast<__nv_bfloat162*>(&Ul[i1]) = __nv_bfloat162(l0, l1);
            } else {
                float* out = (float*)o1;
                size_t i0 = (size_t)z * cZ + (size_t)row * ldc + col;
                size_t i1 = i0 + (size_t)8 * ldc;
                *reinterpret_cast<float2*>(&out[i0]) = make_float2(v0, v1);
                *reinterpret_cast<float2*>(&out[i1]) = make_float2(v2, v3);
            }
        }
    }
}

// ---------------- reduce splits -> bf16-quantized f32 output ----------------
__global__ void reduce_out(float* __restrict__ out) {
    int i = blockIdx.x * blockDim.x + threadIdx.x;
    if (i >= LSEQ * DDIM) return;
    float v = 0.f;
#pragma unroll
    for (int s = 0; s < NSPL; s++) v += d_Upart[(size_t)s * LSEQ * DDIM + i];
    out[i] = __bfloat162float(__float2bfloat16(v));
}

// ---------------- launch ----------------
extern "C" void kernel_launch(void* const* d_in, const int* in_sizes, int n_in,
                              void* d_out, int out_size) {
    int ix = -1, ipos = -1, iC = -1, iM = -1, i512a = -1, i512b = -1, iph1 = -1, iph2 = -1;
    for (int i = 0; i < n_in; i++) {
        int s = in_sizes[i];
        if (s == 1048576)      ix = i;
        else if (s == 2048)    ipos = i;
        else if (s == 24576)   iC = i;
        else if (s == 768)     iM = i;
        else if (s == 512)     { if (i512a < 0) i512a = i; else i512b = i; }
        else if (s == 6291456) { if (iph1 < 0) iph1 = i; else iph2 = i; }
    }
    int iMp, iMm;
    if (iph1 > ipos) { iMp = iph1; iMm = iph2; }
    else             { iMm = iph1; iMp = iph2; }

    const float* x  = (const float*)d_in[ix];
    const float* c0 = (const float*)d_in[i512a];
    const float* c1 = (const float*)d_in[i512b];
    const float* C  = (const float*)d_in[iC];
    const float* M  = (const float*)d_in[iM];
    const float* Mp = (const float*)d_in[iMp];
    const float* Mm = (const float*)d_in[iMm];
    float* out      = (float*)d_out;
    (void)out_size;

    float *pR, *pUpart;
    __nv_bfloat16 *pWh, *pWl, *pBh, *pBl, *pUh, *pUl, *pPh, *pPl;
    cudaGetSymbolAddress((void**)&pR, d_R);
    cudaGetSymbolAddress((void**)&pUpart, d_Upart);
    cudaGetSymbolAddress((void**)&pWh, d_Wh);
    cudaGetSymbolAddress((void**)&pWl, d_Wl);
    cudaGetSymbolAddress((void**)&pBh, d_Bh);
    cudaGetSymbolAddress((void**)&pBl, d_Bl);
    cudaGetSymbolAddress((void**)&pUh, d_Uh);
    cudaGetSymbolAddress((void**)&pUl, d_Ul);
    cudaGetSymbolAddress((void**)&pPh, d_Ph);
    cudaGetSymbolAddress((void**)&pPl, d_Pl);

    // prep
    pick_AB<<<1, 1>>>(c0, c1);
    prep_pow<<<1, 512>>>();
    prep_kbase<<<(TWOK * TCH + 255) / 256, 256>>>(C);
    prep_qmat<<<(SDIM * TCH + 255) / 256, 256>>>();
    prep_wbig<<<(RC * KCP + 255) / 256, 256>>>(C, M);
    prep_phi<<<(int)(((size_t)KF * DDIM + 255) / 256), 256>>>(Mp, Mm);

    // 1) R[c] = Qmat @ X_c (exact fp32)
    {
        LA_Qmat la; LB_X lb{x};
        dim3 grid(DDIM / 64, SDIM / 128, NCH);
        gemm_f32<<<grid, 256>>>(la, lb, pR, (size_t)SDIM * DDIM, DDIM, TCH);
    }
    // 2) chunk-state scan
    scan_chunks<<<(SDIM * DDIM + 255) / 256, 256>>>();
    // 3) build split RHS
    prep_bmat<<<(NCH * KCP * DDIM + 255) / 256, 256>>>(x);

    // 4) chunk GEMM (tensor): U = Wbig @ Bmat_z, split-bf16 epilogue
    {
        dim3 grid(DDIM / 128, RC / 128, NCH);
        mma_gemm<0><<<grid, 256>>>(pWh, pWl, KCP, 0L,
                                   pBh, pBl, DDIM, (long)KCP * DDIM,
                                   pUh, pUl, DDIM, (long)RC * DDIM, KCP / 32);
    }

    // 5) final GEMM (tensor, split-K=8): Upart_z = U[:, zK:(z+1)K] @ Phi[zK:...]
    {
        dim3 grid(DDIM / 128, LSEQ / 128, NSPL);
        mma_gemm<1><<<grid, 256>>>(pUh, pUl, KF, (long)KSPL,
                                   pPh, pPl, DDIM, (long)KSPL * DDIM,
                                   pUpart, nullptr, DDIM, (long)LSEQ * DDIM, KSPL / 32);
    }

    // 6) reduce -> f32 out (bf16-quantized values)
    reduce_out<<<(LSEQ * DDIM + 255) / 256, 256>>>(out);
}